// round 10
// baseline (speedup 1.0000x reference)
#include <cuda_runtime.h>
#include <cstdint>

// B=32, N=64, D=512
// score[b,i,j] = (dot(s_e[b,i,j,:], W) + bias) * adj[b,i,j], adj[b,0,1]=adj[b,1,0]=0
// Only i in {0,1} consumed. Outputs (float32, flattened tuple order):
//   final_id (32,2)=64 | s_e_score (32,2,64)=4096 | flag (32)=32

#define NB 32
#define NN 64
#define ND 512
#define GRID 128
#define TPB  512      // 16 warps; block copies 32 dot-rows (64KB) via cp.async
#define SMEM_BYTES (32 * ND * 4)   // 65536

__device__ int g_done_counter = 0;   // reset by last block each launch

__device__ __forceinline__ uint32_t smem_u32(const void* p) {
    uint32_t a;
    asm("{ .reg .u64 t; cvta.to.shared.u64 t, %1; cvt.u32.u64 %0, t; }"
        : "=r"(a) : "l"(p));
    return a;
}
__device__ __forceinline__ void cp_async16(uint32_t saddr, const void* gptr) {
    asm volatile("cp.async.cg.shared.global [%0], [%1], 16;"
                 :: "r"(saddr), "l"(gptr));
}

__global__ void
fused_kernel(const float* __restrict__ s_e,
             const float* __restrict__ adj,
             const float* __restrict__ W,
             const float* __restrict__ bias,
             float* __restrict__ out_id,
             float* __restrict__ out_score,
             float* __restrict__ out_flag) {
    extern __shared__ float smem[];          // 32 rows x 512 floats
    int tid  = threadIdx.x;
    int warp = tid >> 5;
    int lane = tid & 31;

    // Block's 32 consecutive dots p0..p0+31 share one (b, i); j spans 32 values.
    int p0     = blockIdx.x * 32;
    int b_blk  = p0 >> 7;
    int i_blk  = (p0 >> 6) & 1;
    int j_blk  = p0 & 63;                    // 0 or 32

    // s_e row index for dot p is (b*NN + i)*NN + j  (NOT p itself!)
    const char* gbase =
        (const char*)(s_e + ((size_t)((b_blk * NN + i_blk) * NN + j_blk)) * ND);

    // ---- Post the entire 64KB as 8 cp.async per thread (reg-free MLP) ----
    uint32_t sbase = smem_u32(smem);
#pragma unroll
    for (int k = 0; k < 8; ++k) {
        int off = (k * TPB + tid) * 16;      // byte offset, 0..65520
        cp_async16(sbase + off, gbase + off);
    }
    asm volatile("cp.async.commit_group;" ::: "memory");

    // ---- Overlap: W, bias, adj loads while the bulk copy flies ----
    int j0 = j_blk + warp * 2;               // this warp's first j
    float adj_mine = 0.f;
    if (lane < 2)
        adj_mine = adj[(b_blk * NN + i_blk) * NN + j0 + lane];
    float bias0 = __ldg(bias);
    const float4* wv = (const float4*)W;
    float4 w0 = __ldg(wv + lane);
    float4 w1 = __ldg(wv + 32 + lane);
    float4 w2 = __ldg(wv + 64 + lane);
    float4 w3 = __ldg(wv + 96 + lane);

    asm volatile("cp.async.wait_group 0;" ::: "memory");
    __syncthreads();

    // ---- Compute 2 dots per warp from smem ----
    const float4* s0p = (const float4*)(smem + (warp * 2) * ND);
    const float4* s1p = s0p + (ND / 4);
    float4 a0 = s0p[lane],      a1 = s0p[32 + lane],
           a2 = s0p[64 + lane], a3 = s0p[96 + lane];
    float4 c0 = s1p[lane],      c1 = s1p[32 + lane],
           c2 = s1p[64 + lane], c3 = s1p[96 + lane];

    float s0 = a0.x * w0.x + a0.y * w0.y + a0.z * w0.z + a0.w * w0.w
             + a1.x * w1.x + a1.y * w1.y + a1.z * w1.z + a1.w * w1.w
             + a2.x * w2.x + a2.y * w2.y + a2.z * w2.z + a2.w * w2.w
             + a3.x * w3.x + a3.y * w3.y + a3.z * w3.z + a3.w * w3.w;
    float s1 = c0.x * w0.x + c0.y * w0.y + c0.z * w0.z + c0.w * w0.w
             + c1.x * w1.x + c1.y * w1.y + c1.z * w1.z + c1.w * w1.w
             + c2.x * w2.x + c2.y * w2.y + c2.z * w2.z + c2.w * w2.w
             + c3.x * w3.x + c3.y * w3.y + c3.z * w3.z + c3.w * w3.w;

#pragma unroll
    for (int off = 16; off; off >>= 1) {
        s0 += __shfl_xor_sync(0xffffffffu, s0, off);
        s1 += __shfl_xor_sync(0xffffffffu, s1, off);
    }
    float adj0 = __shfl_sync(0xffffffffu, adj_mine, 0);
    float adj1 = __shfl_sync(0xffffffffu, adj_mine, 1);

    if (lane == 0) {
        if (i_blk == 0 && j0 == 0) adj1 = 0.f;   // (i=0, j=1)
        if (i_blk == 1 && j0 == 0) adj0 = 0.f;   // (i=1, j=0)
        float2 sc = make_float2((s0 + bias0) * adj0, (s1 + bias0) * adj1);
        *(float2*)(out_score + p0 + warp * 2) = sc;   // even -> 8B aligned
    }

    // ---- Handshake: last block runs the epilogue ----
    __syncthreads();
    __shared__ bool is_last;
    if (tid == 0) {
        __threadfence();
        int prev = atomicAdd(&g_done_counter, 1);
        is_last = (prev == GRID - 1);
    }
    __syncthreads();
    if (!is_last) return;
    __threadfence();   // acquire

    // ---- Epilogue: 64 row argmaxes + flags (16 warps x 4 rows, L2-hot) ----
    __shared__ int s_ids[64];
#pragma unroll
    for (int r = 0; r < 4; ++r) {
        int row = warp * 4 + r;               // 0..63 == b*2 + i
        const float* rp = out_score + row * NN;
        float v0 = rp[lane];
        float v1 = rp[lane + 32];
        float v; int idx;
        if (v1 > v0) { v = v1; idx = lane + 32; }
        else         { v = v0; idx = lane; }
#pragma unroll
        for (int off = 16; off; off >>= 1) {
            float ov = __shfl_xor_sync(0xffffffffu, v, off);
            int   oi = __shfl_xor_sync(0xffffffffu, idx, off);
            if (ov > v || (ov == v && oi < idx)) { v = ov; idx = oi; }
        }
        if (lane == 0) {
            s_ids[row] = idx;
            out_id[row] = (float)idx;
        }
    }
    __syncthreads();

    if (tid < NB) {
        int sub = s_ids[tid * 2];
        int obj = s_ids[tid * 2 + 1];
        float f = 0.f;
        if (sub > 0 && obj > 0)      f = 3.f;
        else if (sub > 0)            f = 1.f;
        else if (obj > 0)            f = 2.f;
        out_flag[tid] = f;
    }

    if (tid == 0) g_done_counter = 0;         // deterministic replays
}

extern "C" void kernel_launch(void* const* d_in, const int* in_sizes, int n_in,
                              void* d_out, int out_size) {
    const float* s_e  = (const float*)d_in[0];
    const float* adj  = (const float*)d_in[1];
    const float* W    = (const float*)d_in[2];
    const float* bias = (const float*)d_in[3];

    float* out       = (float*)d_out;
    float* out_id    = out;             // 64
    float* out_score = out + 64;        // 4096
    float* out_flag  = out + 64 + 4096; // 32

    cudaFuncSetAttribute(fused_kernel,
                         cudaFuncAttributeMaxDynamicSharedMemorySize, SMEM_BYTES);
    fused_kernel<<<GRID, TPB, SMEM_BYTES>>>(s_e, adj, W, bias,
                                            out_id, out_score, out_flag);
}

// round 11
// speedup vs baseline: 1.0209x; 1.0209x over previous
#include <cuda_runtime.h>
#include <cstdint>

// B=32, N=64, D=512
// score[b,i,j] = (dot(s_e[b,i,j,:], W) + bias) * adj[b,i,j], adj[b,0,1]=adj[b,1,0]=0
// Only i in {0,1} consumed. Outputs (float32, flattened tuple order):
//   final_id (32,2)=64 | s_e_score (32,2,64)=4096 | flag (32)=32

#define NB 32
#define NN 64
#define ND 512
#define GRID 128
#define TPB  512                    // 16 warps; block handles 32 dot-rows (64KB)
#define SLAB_BYTES (32 * ND * 4)    // 65536
#define SMEM_BYTES SLAB_BYTES

__device__ int g_done_counter = 0;  // reset by last block each launch

__device__ __forceinline__ uint32_t smem_u32(const void* p) {
    uint32_t a;
    asm("{ .reg .u64 t; cvta.to.shared.u64 t, %1; cvt.u32.u64 %0, t; }"
        : "=r"(a) : "l"(p));
    return a;
}

__global__ void
fused_kernel(const float* __restrict__ s_e,
             const float* __restrict__ adj,
             const float* __restrict__ W,
             const float* __restrict__ bias,
             float* __restrict__ out_id,
             float* __restrict__ out_score,
             float* __restrict__ out_flag) {
    extern __shared__ float smem[];             // 32 rows x 512 floats
    __shared__ uint64_t mbar;                   // TMA completion barrier
    int tid  = threadIdx.x;
    int warp = tid >> 5;
    int lane = tid & 31;

    // Block's 32 consecutive dots p0..p0+31 share one (b, i); j spans 32 values.
    int p0    = blockIdx.x * 32;
    int b_blk = p0 >> 7;
    int i_blk = (p0 >> 6) & 1;
    int j_blk = p0 & 63;                        // 0 or 32

    const float* gbase =
        s_e + ((size_t)((b_blk * NN + i_blk) * NN + j_blk)) * ND;

    uint32_t mbar_a = smem_u32(&mbar);
    uint32_t sdst   = smem_u32(smem);

    if (tid == 0) {
        asm volatile("mbarrier.init.shared.b64 [%0], 1;" :: "r"(mbar_a) : "memory");
    }
    __syncthreads();                            // init visible to all waiters

    if (tid == 0) {
        asm volatile("mbarrier.arrive.expect_tx.shared.b64 _, [%0], %1;"
                     :: "r"(mbar_a), "r"((uint32_t)SLAB_BYTES) : "memory");
        asm volatile(
            "cp.async.bulk.shared::cta.global.mbarrier::complete_tx::bytes "
            "[%0], [%1], %2, [%3];"
            :: "r"(sdst), "l"(gbase), "r"((uint32_t)SLAB_BYTES), "r"(mbar_a)
            : "memory");
    }

    // ---- Overlap: W, bias, adj while the 64KB bulk copy flies ----
    int j0 = j_blk + warp * 2;                  // this warp's first j
    float adj_mine = 0.f;
    if (lane < 2)
        adj_mine = adj[(b_blk * NN + i_blk) * NN + j0 + lane];
    float bias0 = __ldg(bias);
    const float4* wv = (const float4*)W;
    float4 w0 = __ldg(wv + lane);
    float4 w1 = __ldg(wv + 32 + lane);
    float4 w2 = __ldg(wv + 64 + lane);
    float4 w3 = __ldg(wv + 96 + lane);

    // ---- Wait for bulk copy (parity 0; mbarrier re-inited every launch) ----
    {
        uint32_t done;
        asm volatile(
            "{\n\t.reg .pred p;\n\t"
            "mbarrier.try_wait.parity.acquire.cta.shared::cta.b64 p, [%1], 0;\n\t"
            "selp.b32 %0, 1, 0, p;\n\t}"
            : "=r"(done) : "r"(mbar_a) : "memory");
        while (!done) {
            asm volatile(
                "{\n\t.reg .pred p;\n\t"
                "mbarrier.try_wait.parity.acquire.cta.shared::cta.b64 p, [%1], 0, 0x989680;\n\t"
                "selp.b32 %0, 1, 0, p;\n\t}"
                : "=r"(done) : "r"(mbar_a) : "memory");
        }
    }

    // ---- Compute 2 dots per warp from smem ----
    const float4* s0p = (const float4*)(smem + (warp * 2) * ND);
    const float4* s1p = s0p + (ND / 4);
    float4 a0 = s0p[lane],      a1 = s0p[32 + lane],
           a2 = s0p[64 + lane], a3 = s0p[96 + lane];
    float4 c0 = s1p[lane],      c1 = s1p[32 + lane],
           c2 = s1p[64 + lane], c3 = s1p[96 + lane];

    float s0 = a0.x * w0.x + a0.y * w0.y + a0.z * w0.z + a0.w * w0.w
             + a1.x * w1.x + a1.y * w1.y + a1.z * w1.z + a1.w * w1.w
             + a2.x * w2.x + a2.y * w2.y + a2.z * w2.z + a2.w * w2.w
             + a3.x * w3.x + a3.y * w3.y + a3.z * w3.z + a3.w * w3.w;
    float s1 = c0.x * w0.x + c0.y * w0.y + c0.z * w0.z + c0.w * w0.w
             + c1.x * w1.x + c1.y * w1.y + c1.z * w1.z + c1.w * w1.w
             + c2.x * w2.x + c2.y * w2.y + c2.z * w2.z + c2.w * w2.w
             + c3.x * w3.x + c3.y * w3.y + c3.z * w3.z + c3.w * w3.w;

#pragma unroll
    for (int off = 16; off; off >>= 1) {
        s0 += __shfl_xor_sync(0xffffffffu, s0, off);
        s1 += __shfl_xor_sync(0xffffffffu, s1, off);
    }
    float adj0 = __shfl_sync(0xffffffffu, adj_mine, 0);
    float adj1 = __shfl_sync(0xffffffffu, adj_mine, 1);

    if (lane == 0) {
        if (i_blk == 0 && j0 == 0) adj1 = 0.f;   // (i=0, j=1)
        if (i_blk == 1 && j0 == 0) adj0 = 0.f;   // (i=1, j=0)
        float2 sc = make_float2((s0 + bias0) * adj0, (s1 + bias0) * adj1);
        *(float2*)(out_score + p0 + warp * 2) = sc;   // even -> 8B aligned
    }

    // ---- Handshake: last block runs the epilogue ----
    __syncthreads();
    __shared__ bool is_last;
    if (tid == 0) {
        __threadfence();
        int prev = atomicAdd(&g_done_counter, 1);
        is_last = (prev == GRID - 1);
    }
    __syncthreads();
    if (!is_last) return;
    __threadfence();   // acquire

    // ---- Epilogue: 64 row argmaxes + flags (16 warps x 4 rows, L2-hot) ----
    __shared__ int s_ids[64];
#pragma unroll
    for (int r = 0; r < 4; ++r) {
        int row = warp * 4 + r;                  // 0..63 == b*2 + i
        const float* rp = out_score + row * NN;
        float v0 = rp[lane];
        float v1 = rp[lane + 32];
        float v; int idx;
        if (v1 > v0) { v = v1; idx = lane + 32; }
        else         { v = v0; idx = lane; }
#pragma unroll
        for (int off = 16; off; off >>= 1) {
            float ov = __shfl_xor_sync(0xffffffffu, v, off);
            int   oi = __shfl_xor_sync(0xffffffffu, idx, off);
            if (ov > v || (ov == v && oi < idx)) { v = ov; idx = oi; }
        }
        if (lane == 0) {
            s_ids[row] = idx;
            out_id[row] = (float)idx;
        }
    }
    __syncthreads();

    if (tid < NB) {
        int sub = s_ids[tid * 2];
        int obj = s_ids[tid * 2 + 1];
        float f = 0.f;
        if (sub > 0 && obj > 0)      f = 3.f;
        else if (sub > 0)            f = 1.f;
        else if (obj > 0)            f = 2.f;
        out_flag[tid] = f;
    }

    if (tid == 0) g_done_counter = 0;            // deterministic replays
}

extern "C" void kernel_launch(void* const* d_in, const int* in_sizes, int n_in,
                              void* d_out, int out_size) {
    const float* s_e  = (const float*)d_in[0];
    const float* adj  = (const float*)d_in[1];
    const float* W    = (const float*)d_in[2];
    const float* bias = (const float*)d_in[3];

    float* out       = (float*)d_out;
    float* out_id    = out;             // 64
    float* out_score = out + 64;        // 4096
    float* out_flag  = out + 64 + 4096; // 32

    cudaFuncSetAttribute(fused_kernel,
                         cudaFuncAttributeMaxDynamicSharedMemorySize, SMEM_BYTES);
    fused_kernel<<<GRID, TPB, SMEM_BYTES>>>(s_e, adj, W, bias,
                                            out_id, out_score, out_flag);
}

// round 12
// speedup vs baseline: 1.2258x; 1.2007x over previous
#include <cuda_runtime.h>
#include <cstdint>

// B=32, N=64, D=512
// score[b,i,j] = (dot(s_e[b,i,j,:], W) + bias) * adj[b,i,j], adj[b,0,1]=adj[b,1,0]=0
// Only i in {0,1} consumed. Outputs (float32, flattened tuple order):
//   final_id (32,2)=64 | s_e_score (32,2,64)=4096 | flag (32)=32

#define NB 32
#define NN 64
#define ND 512
#define GRID 64     // one block per output row (b*2+i)
#define TPB  1024   // 32 warps x 2 dots = the row's 64 dot products

__device__ int g_pair[NB] = {};   // per-batch arrival counter (reset by consumer)
__device__ int g_ids[NB * 2];     // int mirror of final_id (overwritten each launch)

__global__ void __launch_bounds__(TPB, 1)
fused_kernel(const float* __restrict__ s_e,
             const float* __restrict__ adj,
             const float* __restrict__ W,
             const float* __restrict__ bias,
             float* __restrict__ out_id,
             float* __restrict__ out_score,
             float* __restrict__ out_flag) {
    int warp = threadIdx.x >> 5;
    int lane = threadIdx.x & 31;

    int row = blockIdx.x;            // 0..63 == b*2 + i
    int b   = row >> 1;
    int i   = row & 1;
    int j0  = warp * 2;              // this warp's two j's: j0, j0+1

    __shared__ float s_score[NN];

    // ---------- FRONT-BATCH ALL LOADS (single latency exposure) ----------
    const float4* base0 =
        (const float4*)(s_e + ((size_t)((b * NN + i) * NN + j0)) * ND);
    const float4* base1 = base0 + (ND / 4);      // j0+1 (contiguous)
    const float4* wv = (const float4*)W;

    float adj_mine = 0.f;
    if (lane < 2)
        adj_mine = adj[(b * NN + i) * NN + j0 + lane];
    float bias0 = __ldg(bias);

    float4 a0 = base0[lane];
    float4 a1 = base0[32 + lane];
    float4 a2 = base0[64 + lane];
    float4 a3 = base0[96 + lane];
    float4 c0 = base1[lane];
    float4 c1 = base1[32 + lane];
    float4 c2 = base1[64 + lane];
    float4 c3 = base1[96 + lane];
    float4 w0 = wv[lane];
    float4 w1 = wv[32 + lane];
    float4 w2 = wv[64 + lane];
    float4 w3 = wv[96 + lane];

    float s0 = a0.x * w0.x + a0.y * w0.y + a0.z * w0.z + a0.w * w0.w
             + a1.x * w1.x + a1.y * w1.y + a1.z * w1.z + a1.w * w1.w
             + a2.x * w2.x + a2.y * w2.y + a2.z * w2.z + a2.w * w2.w
             + a3.x * w3.x + a3.y * w3.y + a3.z * w3.z + a3.w * w3.w;
    float s1 = c0.x * w0.x + c0.y * w0.y + c0.z * w0.z + c0.w * w0.w
             + c1.x * w1.x + c1.y * w1.y + c1.z * w1.z + c1.w * w1.w
             + c2.x * w2.x + c2.y * w2.y + c2.z * w2.z + c2.w * w2.w
             + c3.x * w3.x + c3.y * w3.y + c3.z * w3.z + c3.w * w3.w;

#pragma unroll
    for (int off = 16; off; off >>= 1) {
        s0 += __shfl_xor_sync(0xffffffffu, s0, off);
        s1 += __shfl_xor_sync(0xffffffffu, s1, off);
    }
    float adj0 = __shfl_sync(0xffffffffu, adj_mine, 0);
    float adj1 = __shfl_sync(0xffffffffu, adj_mine, 1);

    if (lane == 0) {
        if (j0 == 0) {                           // zero (0,1)/(1,0) entries
            if (i == 0) adj1 = 0.f;              // j = 1
            else        adj0 = 0.f;              // j = 0
        }
        float sc0 = (s0 + bias0) * adj0;
        float sc1 = (s1 + bias0) * adj1;
        *(float2*)(out_score + row * NN + j0) = make_float2(sc0, sc1);
        s_score[j0]     = sc0;
        s_score[j0 + 1] = sc1;
    }
    __syncthreads();

    // ---------- warp 0: row argmax from SMEM (no L2 round-trip) ----------
    if (warp == 0) {
        float v0 = s_score[lane];
        float v1 = s_score[lane + 32];
        float v; int idx;
        if (v1 > v0) { v = v1; idx = lane + 32; }
        else         { v = v0; idx = lane; }
#pragma unroll
        for (int off = 16; off; off >>= 1) {
            float ov = __shfl_xor_sync(0xffffffffu, v, off);
            int   oi = __shfl_xor_sync(0xffffffffu, idx, off);
            if (ov > v || (ov == v && oi < idx)) { v = ov; idx = oi; }
        }
        if (lane == 0) {
            out_id[row] = (float)idx;
            g_ids[row]  = idx;
            __threadfence();                     // publish before pairing
            int prev = atomicAdd(&g_pair[b], 1);
            if (prev == 1) {                     // partner row already done
                __threadfence();                 // acquire partner's g_ids write
                int other = g_ids[row ^ 1];
                int sub = (i == 0) ? idx   : other;
                int obj = (i == 0) ? other : idx;
                float f = 0.f;
                if (sub > 0 && obj > 0)      f = 3.f;
                else if (sub > 0)            f = 1.f;
                else if (obj > 0)            f = 2.f;
                out_flag[b] = f;
                g_pair[b] = 0;                   // reset for next replay
            }
        }
    }
}

extern "C" void kernel_launch(void* const* d_in, const int* in_sizes, int n_in,
                              void* d_out, int out_size) {
    const float* s_e  = (const float*)d_in[0];
    const float* adj  = (const float*)d_in[1];
    const float* W    = (const float*)d_in[2];
    const float* bias = (const float*)d_in[3];

    float* out       = (float*)d_out;
    float* out_id    = out;             // 64
    float* out_score = out + 64;        // 4096
    float* out_flag  = out + 64 + 4096; // 32

    fused_kernel<<<GRID, TPB>>>(s_e, adj, W, bias, out_id, out_score, out_flag);
}